// round 1
// baseline (speedup 1.0000x reference)
#include <cuda_runtime.h>
#include <math.h>

#define N_NODES 100000
#define N_EDGES 1600000
#define CHN 128
#define OUTCH 64

// ---------------- device scratch (static allocation; no cudaMalloc) -------
__device__ int   g_is64;
__device__ int   g_cnt[N_NODES];
__device__ int   g_row[N_NODES + 1];
__device__ int   g_cur[N_NODES];
__device__ float g_dis[N_NODES];
__device__ int   g_csr[N_EDGES];
__device__ float g_hs[N_NODES * CHN];
__device__ float g_x1[N_NODES * CHN];
__device__ float g_x2[N_NODES * CHN];

// ---------------- CSR build ----------------------------------------------
// Zero the per-node counters; thread 0 also sniffs the edge dtype:
// if edge_index is int64 (values < 2^31), every odd 32-bit word is 0.
__global__ void k_init(const void* __restrict__ edges) {
    int i = blockIdx.x * blockDim.x + threadIdx.x;
    if (i < N_NODES) g_cnt[i] = 0;
    if (i == 0) {
        const int* p = (const int*)edges;
        int zeros = 0;
        for (int w = 1; w < 2048; w += 2) zeros += (p[w] == 0);
        g_is64 = (zeros > 512) ? 1 : 0;
    }
}

__global__ void k_hist(const void* __restrict__ edges) {
    int i = blockIdx.x * blockDim.x + threadIdx.x;
    if (i >= N_EDGES) return;
    int d;
    if (g_is64) d = (int)((const long long*)edges)[N_EDGES + i];
    else        d = ((const int*)edges)[N_EDGES + i];
    atomicAdd(&g_cnt[d], 1);
}

// Single-block exclusive scan over g_cnt -> g_row / g_cur, plus dis = rsqrt(deg+1)
__global__ void k_scan() {
    __shared__ int s[1024];
    int t = threadIdx.x;
    const int CHK = (N_NODES + 1023) >> 10;   // elements per thread
    int beg = t * CHK;
    int end = beg + CHK; if (end > N_NODES) end = N_NODES;
    int sum = 0;
    for (int i = beg; i < end; i++) sum += g_cnt[i];
    s[t] = sum;
    __syncthreads();
    for (int off = 1; off < 1024; off <<= 1) {
        int v = (t >= off) ? s[t - off] : 0;
        __syncthreads();
        s[t] += v;
        __syncthreads();
    }
    int run = s[t] - sum;                     // exclusive prefix of this chunk
    for (int i = beg; i < end; i++) {
        int c = g_cnt[i];
        g_row[i] = run;
        g_cur[i] = run;
        g_dis[i] = rsqrtf((float)(c + 1));
        run += c;
    }
    if (t == 0) g_row[N_NODES] = N_EDGES;
}

__global__ void k_fill(const void* __restrict__ edges) {
    int i = blockIdx.x * blockDim.x + threadIdx.x;
    if (i >= N_EDGES) return;
    int sN, dN;
    if (g_is64) {
        const long long* p = (const long long*)edges;
        sN = (int)p[i]; dN = (int)p[N_EDGES + i];
    } else {
        const int* p = (const int*)edges;
        sN = p[i]; dN = p[N_EDGES + i];
    }
    int idx = atomicAdd(&g_cur[dN], 1);
    g_csr[idx] = sN;
}

// ---------------- GEMM (M x 128) @ (128 x 128), epilogue: *dis[row] -------
__global__ __launch_bounds__(256) void gemm128(
    const float* __restrict__ A, const float* __restrict__ B,
    float* __restrict__ out, const float* __restrict__ dis, int M)
{
    __shared__ float As[16][128];
    __shared__ float Bs[16][128];
    int tid = threadIdx.x;
    int bm = blockIdx.x * 128;
    int tx = tid & 15, ty = tid >> 4;
    float acc[8][8];
#pragma unroll
    for (int i = 0; i < 8; i++)
#pragma unroll
        for (int j = 0; j < 8; j++) acc[i][j] = 0.f;

    int ar = tid >> 2;           // 0..63
    int ac = (tid & 3) * 4;      // 0,4,8,12
    int br = tid >> 5;           // 0..7
    int bc = (tid & 31) * 4;     // 0..124

    for (int k0 = 0; k0 < 128; k0 += 16) {
#pragma unroll
        for (int h = 0; h < 2; h++) {
            int r = bm + ar + h * 64;
            float4 v = make_float4(0.f, 0.f, 0.f, 0.f);
            if (r < M) v = *(const float4*)(A + (long)r * 128 + k0 + ac);
            As[ac + 0][ar + h * 64] = v.x;
            As[ac + 1][ar + h * 64] = v.y;
            As[ac + 2][ar + h * 64] = v.z;
            As[ac + 3][ar + h * 64] = v.w;
        }
#pragma unroll
        for (int h = 0; h < 2; h++) {
            int r = k0 + br + h * 8;
            *(float4*)(&Bs[br + h * 8][bc]) = *(const float4*)(B + r * 128 + bc);
        }
        __syncthreads();
#pragma unroll
        for (int kk = 0; kk < 16; kk++) {
            float a[8], b[8];
            *(float4*)(a)     = *(const float4*)(&As[kk][ty * 8]);
            *(float4*)(a + 4) = *(const float4*)(&As[kk][ty * 8 + 4]);
            *(float4*)(b)     = *(const float4*)(&Bs[kk][tx * 8]);
            *(float4*)(b + 4) = *(const float4*)(&Bs[kk][tx * 8 + 4]);
#pragma unroll
            for (int i = 0; i < 8; i++)
#pragma unroll
                for (int j = 0; j < 8; j++) acc[i][j] += a[i] * b[j];
        }
        __syncthreads();
    }
#pragma unroll
    for (int i = 0; i < 8; i++) {
        int r = bm + ty * 8 + i;
        if (r >= M) continue;
        float d = dis[r];
#pragma unroll
        for (int j = 0; j < 8; j += 4) {
            float4 v;
            v.x = acc[i][j + 0] * d;
            v.y = acc[i][j + 1] * d;
            v.z = acc[i][j + 2] * d;
            v.w = acc[i][j + 3] * d;
            *(float4*)(out + (long)r * 128 + tx * 8 + j) = v;
        }
    }
}

// ---------------- Output GEMM: (x1+x2)[M,128] @ Wo[128,64] + bo ----------
__global__ __launch_bounds__(256) void gemm_out(
    const float* __restrict__ A1, const float* __restrict__ A2,
    const float* __restrict__ B, const float* __restrict__ bias,
    float* __restrict__ out, int M)
{
    __shared__ float As[16][128];
    __shared__ float Bs[16][64];
    int tid = threadIdx.x;
    int bm = blockIdx.x * 128;
    int tx = tid & 15, ty = tid >> 4;
    float acc[8][4];
#pragma unroll
    for (int i = 0; i < 8; i++)
#pragma unroll
        for (int j = 0; j < 4; j++) acc[i][j] = 0.f;

    int ar = tid >> 2;
    int ac = (tid & 3) * 4;
    int br = tid >> 4;          // 0..15
    int bc = (tid & 15) * 4;    // 0..60

    for (int k0 = 0; k0 < 128; k0 += 16) {
#pragma unroll
        for (int h = 0; h < 2; h++) {
            int r = bm + ar + h * 64;
            float4 v = make_float4(0.f, 0.f, 0.f, 0.f);
            if (r < M) {
                float4 u = *(const float4*)(A1 + (long)r * 128 + k0 + ac);
                float4 w = *(const float4*)(A2 + (long)r * 128 + k0 + ac);
                v.x = u.x + w.x; v.y = u.y + w.y; v.z = u.z + w.z; v.w = u.w + w.w;
            }
            As[ac + 0][ar + h * 64] = v.x;
            As[ac + 1][ar + h * 64] = v.y;
            As[ac + 2][ar + h * 64] = v.z;
            As[ac + 3][ar + h * 64] = v.w;
        }
        *(float4*)(&Bs[br][bc]) = *(const float4*)(B + (k0 + br) * 64 + bc);
        __syncthreads();
#pragma unroll
        for (int kk = 0; kk < 16; kk++) {
            float a[8], b[4];
            *(float4*)(a)     = *(const float4*)(&As[kk][ty * 8]);
            *(float4*)(a + 4) = *(const float4*)(&As[kk][ty * 8 + 4]);
            *(float4*)(b)     = *(const float4*)(&Bs[kk][tx * 4]);
#pragma unroll
            for (int i = 0; i < 8; i++)
#pragma unroll
                for (int j = 0; j < 4; j++) acc[i][j] += a[i] * b[j];
        }
        __syncthreads();
    }
#pragma unroll
    for (int i = 0; i < 8; i++) {
        int r = bm + ty * 8 + i;
        if (r >= M) continue;
        float4 v;
        v.x = acc[i][0] + bias[tx * 4 + 0];
        v.y = acc[i][1] + bias[tx * 4 + 1];
        v.z = acc[i][2] + bias[tx * 4 + 2];
        v.w = acc[i][3] + bias[tx * 4 + 3];
        *(float4*)(out + (long)r * 64 + tx * 4) = v;
    }
}

// ---------------- aggregation: warp per node, atomic-free ----------------
// xo[d] = relu(dis[d] * (hs[d] + sum_{s in in(d)} hs[s]) + bias)
__global__ __launch_bounds__(256) void aggregate(
    const float* __restrict__ hs, const float* __restrict__ bias,
    float* __restrict__ xo)
{
    int gw = (blockIdx.x * blockDim.x + threadIdx.x) >> 5;
    int lane = threadIdx.x & 31;
    if (gw >= N_NODES) return;
    int beg = g_row[gw];
    int end = g_row[gw + 1];
    float4 acc = *(const float4*)(hs + (long)gw * 128 + lane * 4);  // self-loop term
    for (int e = beg; e < end; e++) {
        int s = g_csr[e];
        float4 v = *(const float4*)(hs + (long)s * 128 + lane * 4);
        acc.x += v.x; acc.y += v.y; acc.z += v.z; acc.w += v.w;
    }
    float d = g_dis[gw];
    float4 b = *(const float4*)(bias + lane * 4);
    float4 o;
    o.x = fmaxf(acc.x * d + b.x, 0.f);
    o.y = fmaxf(acc.y * d + b.y, 0.f);
    o.z = fmaxf(acc.z * d + b.z, 0.f);
    o.w = fmaxf(acc.w * d + b.w, 0.f);
    *(float4*)(xo + (long)gw * 128 + lane * 4) = o;
}

// ---------------- launch ---------------------------------------------------
extern "C" void kernel_launch(void* const* d_in, const int* in_sizes, int n_in,
                              void* d_out, int out_size)
{
    const float* x  = (const float*)d_in[0];
    const void*  ei = d_in[1];
    const float* W1 = (const float*)d_in[2];
    const float* b1 = (const float*)d_in[3];
    const float* W2 = (const float*)d_in[4];
    const float* b2 = (const float*)d_in[5];
    const float* Wo = (const float*)d_in[6];
    const float* bo = (const float*)d_in[7];
    float* out = (float*)d_out;

    float *hs, *x1, *x2, *dis;
    cudaGetSymbolAddress((void**)&hs,  g_hs);
    cudaGetSymbolAddress((void**)&x1,  g_x1);
    cudaGetSymbolAddress((void**)&x2,  g_x2);
    cudaGetSymbolAddress((void**)&dis, g_dis);

    const int M = N_NODES;
    int gB  = (M + 127) / 128;                 // GEMM blocks
    int gE  = (N_EDGES + 255) / 256;
    int gN  = (M + 255) / 256;
    int gAg = (M * 32 + 255) / 256;            // warp per node

    // CSR build + normalization
    k_init<<<gN, 256>>>(ei);
    k_hist<<<gE, 256>>>(ei);
    k_scan<<<1, 1024>>>();
    k_fill<<<gE, 256>>>(ei);

    // layer 1
    gemm128<<<gB, 256>>>(x, W1, hs, dis, M);
    aggregate<<<gAg, 256>>>(hs, b1, x1);
    // layer 2
    gemm128<<<gB, 256>>>(x1, W2, hs, dis, M);
    aggregate<<<gAg, 256>>>(hs, b2, x2);
    // output projection on (x1 + x2)
    gemm_out<<<gB, 256>>>(x1, x2, Wo, bo, out, M);
}

// round 2
// speedup vs baseline: 1.0514x; 1.0514x over previous
#include <cuda_runtime.h>
#include <mma.h>
#include <math.h>

using namespace nvcuda;

#define N_NODES 100000
#define N_PAD   100096          // padded to multiple of 128 for unguarded tile stores
#define N_EDGES 1600000
#define CHN 128
#define OUTCH 64

// ---------------- device scratch (static allocation; no cudaMalloc) -------
__device__ int   g_is64;
__device__ int   g_cnt[N_NODES];
__device__ int   g_row[N_NODES + 1];
__device__ int   g_cur[N_NODES];
__device__ float g_dis[N_NODES];
__device__ int   g_csr[N_EDGES];
__device__ float g_hs[N_PAD * CHN];
__device__ float g_x1[N_PAD * CHN];
__device__ float g_x2[N_PAD * CHN];

// ---------------- CSR build ----------------------------------------------
__global__ void k_init(const void* __restrict__ edges) {
    int i = blockIdx.x * blockDim.x + threadIdx.x;
    if (i < N_NODES) g_cnt[i] = 0;
    if (i == 0) {
        const int* p = (const int*)edges;
        int zeros = 0;
        for (int w = 1; w < 2048; w += 2) zeros += (p[w] == 0);
        g_is64 = (zeros > 512) ? 1 : 0;
    }
}

__global__ void k_hist(const void* __restrict__ edges) {
    int i = blockIdx.x * blockDim.x + threadIdx.x;
    if (i >= N_EDGES) return;
    int d;
    if (g_is64) d = (int)((const long long*)edges)[N_EDGES + i];
    else        d = ((const int*)edges)[N_EDGES + i];
    atomicAdd(&g_cnt[d], 1);
}

__global__ void k_scan() {
    __shared__ int s[1024];
    int t = threadIdx.x;
    const int CHK = (N_NODES + 1023) >> 10;
    int beg = t * CHK;
    int end = beg + CHK; if (end > N_NODES) end = N_NODES;
    int sum = 0;
    for (int i = beg; i < end; i++) sum += g_cnt[i];
    s[t] = sum;
    __syncthreads();
    for (int off = 1; off < 1024; off <<= 1) {
        int v = (t >= off) ? s[t - off] : 0;
        __syncthreads();
        s[t] += v;
        __syncthreads();
    }
    int run = s[t] - sum;
    for (int i = beg; i < end; i++) {
        int c = g_cnt[i];
        g_row[i] = run;
        g_cur[i] = run;
        g_dis[i] = rsqrtf((float)(c + 1));
        run += c;
    }
    if (t == 0) g_row[N_NODES] = N_EDGES;
}

__global__ void k_fill(const void* __restrict__ edges) {
    int i = blockIdx.x * blockDim.x + threadIdx.x;
    if (i >= N_EDGES) return;
    int sN, dN;
    if (g_is64) {
        const long long* p = (const long long*)edges;
        sN = (int)p[i]; dN = (int)p[N_EDGES + i];
    } else {
        const int* p = (const int*)edges;
        sN = p[i]; dN = p[N_EDGES + i];
    }
    int idx = atomicAdd(&g_cur[dN], 1);
    g_csr[idx] = sN;
}

// ---------------- helpers --------------------------------------------------
template <typename Frag>
__device__ __forceinline__ void frag_to_tf32(Frag& f) {
#pragma unroll
    for (int i = 0; i < f.num_elements; i++) f.x[i] = wmma::__float_to_tf32(f.x[i]);
}

// ---------------- tf32 GEMM: A[M,128] @ B[128,128] -> out (padded) --------
// out rows beyond M land in padding of the __device__ output array (harmless).
__global__ __launch_bounds__(256) void gemm_tf32(
    const float* __restrict__ A, const float* __restrict__ B,
    float* __restrict__ out, int M)
{
    __shared__ float As[128][40];   // [M-tile][K-chunk=32] + pad
    __shared__ float Bs[32][136];   // [K-chunk][N=128] + pad
    int tid = threadIdx.x;
    int wid = tid >> 5;
    int wm = wid & 3;               // warp row: 32 rows each
    int wn = wid >> 2;              // warp col: 64 cols each
    int bm = blockIdx.x * 128;

    wmma::fragment<wmma::accumulator, 16, 16, 8, float> acc[2][4];
#pragma unroll
    for (int i = 0; i < 2; i++)
#pragma unroll
        for (int j = 0; j < 4; j++) wmma::fill_fragment(acc[i][j], 0.f);

    for (int k0 = 0; k0 < 128; k0 += 32) {
        // As: 128x32 = 1024 float4 loads
#pragma unroll
        for (int h = 0; h < 4; h++) {
            int i4 = tid + h * 256;
            int r = i4 >> 3, c = (i4 & 7) * 4;
            float4 v = make_float4(0.f, 0.f, 0.f, 0.f);
            if (bm + r < M) v = *(const float4*)(A + (long)(bm + r) * 128 + k0 + c);
            *(float4*)(&As[r][c]) = v;
        }
        // Bs: 32x128 = 1024 float4 loads
#pragma unroll
        for (int h = 0; h < 4; h++) {
            int i4 = tid + h * 256;
            int r = i4 >> 5, c = (i4 & 31) * 4;
            *(float4*)(&Bs[r][c]) = *(const float4*)(B + (long)(k0 + r) * 128 + c);
        }
        __syncthreads();
#pragma unroll
        for (int kk = 0; kk < 4; kk++) {
            wmma::fragment<wmma::matrix_a, 16, 16, 8, wmma::precision::tf32, wmma::row_major> af[2];
            wmma::fragment<wmma::matrix_b, 16, 16, 8, wmma::precision::tf32, wmma::row_major> bf[4];
#pragma unroll
            for (int i = 0; i < 2; i++) {
                wmma::load_matrix_sync(af[i], &As[wm * 32 + i * 16][kk * 8], 40);
                frag_to_tf32(af[i]);
            }
#pragma unroll
            for (int j = 0; j < 4; j++) {
                wmma::load_matrix_sync(bf[j], &Bs[kk * 8][wn * 64 + j * 16], 136);
                frag_to_tf32(bf[j]);
            }
#pragma unroll
            for (int i = 0; i < 2; i++)
#pragma unroll
                for (int j = 0; j < 4; j++)
                    wmma::mma_sync(acc[i][j], af[i], bf[j], acc[i][j]);
        }
        __syncthreads();
    }
#pragma unroll
    for (int i = 0; i < 2; i++)
#pragma unroll
        for (int j = 0; j < 4; j++) {
            int r = bm + wm * 32 + i * 16;
            wmma::store_matrix_sync(out + (long)r * 128 + wn * 64 + j * 16,
                                    acc[i][j], 128, wmma::mem_row_major);
        }
}

// ---------------- tf32 output GEMM: (x1+x2)[M,128] @ Wo[128,64] + bo ------
__global__ __launch_bounds__(256) void gemm_out_tf32(
    const float* __restrict__ A1, const float* __restrict__ A2,
    const float* __restrict__ B, const float* __restrict__ bias,
    float* __restrict__ out, int M)
{
    __shared__ float As[128][40];
    __shared__ float Bs[32][72];
    __shared__ float Bt[16][72];    // bias tile, rows replicated
    int tid = threadIdx.x;
    int wid = tid >> 5;             // 0..7, each warp = 16 rows, all 64 cols
    int bm = blockIdx.x * 128;

    // bias tile
    for (int i = tid; i < 16 * 64; i += 256) Bt[i >> 6][i & 63] = bias[i & 63];
    __syncthreads();

    wmma::fragment<wmma::accumulator, 16, 16, 8, float> acc[4];
#pragma unroll
    for (int j = 0; j < 4; j++)
        wmma::load_matrix_sync(acc[j], &Bt[0][j * 16], 72, wmma::mem_row_major);

    for (int k0 = 0; k0 < 128; k0 += 32) {
#pragma unroll
        for (int h = 0; h < 4; h++) {
            int i4 = tid + h * 256;
            int r = i4 >> 3, c = (i4 & 7) * 4;
            float4 v = make_float4(0.f, 0.f, 0.f, 0.f);
            if (bm + r < M) {
                float4 u = *(const float4*)(A1 + (long)(bm + r) * 128 + k0 + c);
                float4 w = *(const float4*)(A2 + (long)(bm + r) * 128 + k0 + c);
                v.x = u.x + w.x; v.y = u.y + w.y; v.z = u.z + w.z; v.w = u.w + w.w;
            }
            *(float4*)(&As[r][c]) = v;
        }
        // Bs: 32x64 = 512 float4 loads
        {
            int i4 = tid + 0;
            int r = i4 >> 4, c = (i4 & 15) * 4;
            *(float4*)(&Bs[r][c]) = *(const float4*)(B + (long)(k0 + r) * 64 + c);
            i4 = tid + 256;
            r = i4 >> 4; c = (i4 & 15) * 4;
            *(float4*)(&Bs[r][c]) = *(const float4*)(B + (long)(k0 + r) * 64 + c);
        }
        __syncthreads();
#pragma unroll
        for (int kk = 0; kk < 4; kk++) {
            wmma::fragment<wmma::matrix_a, 16, 16, 8, wmma::precision::tf32, wmma::row_major> af;
            wmma::fragment<wmma::matrix_b, 16, 16, 8, wmma::precision::tf32, wmma::row_major> bf[4];
            wmma::load_matrix_sync(af, &As[wid * 16][kk * 8], 40);
            frag_to_tf32(af);
#pragma unroll
            for (int j = 0; j < 4; j++) {
                wmma::load_matrix_sync(bf[j], &Bs[kk * 8][j * 16], 72);
                frag_to_tf32(bf[j]);
            }
#pragma unroll
            for (int j = 0; j < 4; j++)
                wmma::mma_sync(acc[j], af, bf[j], acc[j]);
        }
        __syncthreads();
    }
    int r = bm + wid * 16;
    if (r + 16 <= M) {              // M % 16 == 0 so fragments never split
#pragma unroll
        for (int j = 0; j < 4; j++)
            wmma::store_matrix_sync(out + (long)r * 64 + j * 16,
                                    acc[j], 64, wmma::mem_row_major);
    }
}

// ---------------- aggregation: warp per node, atomic-free ----------------
// xo[d] = relu(dis[d] * (h[d]*dis[d] + sum_s h[s]*dis[s]) + bias)
__global__ __launch_bounds__(256) void aggregate(
    const float* __restrict__ hs, const float* __restrict__ bias,
    float* __restrict__ xo)
{
    int gw = (blockIdx.x * blockDim.x + threadIdx.x) >> 5;
    int lane = threadIdx.x & 31;
    if (gw >= N_NODES) return;
    int beg = g_row[gw];
    int end = g_row[gw + 1];
    float dd = g_dis[gw];
    float4 self = *(const float4*)(hs + (long)gw * 128 + lane * 4);
    float4 acc;
    acc.x = self.x * dd; acc.y = self.y * dd; acc.z = self.z * dd; acc.w = self.w * dd;
    int e = beg;
    for (; e + 2 <= end; e += 2) {
        int s0 = g_csr[e], s1 = g_csr[e + 1];
        float d0 = g_dis[s0], d1 = g_dis[s1];
        float4 v0 = *(const float4*)(hs + (long)s0 * 128 + lane * 4);
        float4 v1 = *(const float4*)(hs + (long)s1 * 128 + lane * 4);
        acc.x += v0.x * d0 + v1.x * d1;
        acc.y += v0.y * d0 + v1.y * d1;
        acc.z += v0.z * d0 + v1.z * d1;
        acc.w += v0.w * d0 + v1.w * d1;
    }
    if (e < end) {
        int s = g_csr[e];
        float ds = g_dis[s];
        float4 v = *(const float4*)(hs + (long)s * 128 + lane * 4);
        acc.x += v.x * ds; acc.y += v.y * ds; acc.z += v.z * ds; acc.w += v.w * ds;
    }
    float4 b = *(const float4*)(bias + lane * 4);
    float4 o;
    o.x = fmaxf(acc.x * dd + b.x, 0.f);
    o.y = fmaxf(acc.y * dd + b.y, 0.f);
    o.z = fmaxf(acc.z * dd + b.z, 0.f);
    o.w = fmaxf(acc.w * dd + b.w, 0.f);
    *(float4*)(xo + (long)gw * 128 + lane * 4) = o;
}

// ---------------- launch ---------------------------------------------------
extern "C" void kernel_launch(void* const* d_in, const int* in_sizes, int n_in,
                              void* d_out, int out_size)
{
    const float* x  = (const float*)d_in[0];
    const void*  ei = d_in[1];
    const float* W1 = (const float*)d_in[2];
    const float* b1 = (const float*)d_in[3];
    const float* W2 = (const float*)d_in[4];
    const float* b2 = (const float*)d_in[5];
    const float* Wo = (const float*)d_in[6];
    const float* bo = (const float*)d_in[7];
    float* out = (float*)d_out;

    float *hs, *x1, *x2;
    cudaGetSymbolAddress((void**)&hs, g_hs);
    cudaGetSymbolAddress((void**)&x1, g_x1);
    cudaGetSymbolAddress((void**)&x2, g_x2);

    const int M = N_NODES;
    int gB  = (M + 127) / 128;
    int gE  = (N_EDGES + 255) / 256;
    int gN  = (M + 255) / 256;
    int gAg = (M * 32 + 255) / 256;

    // CSR build + normalization
    k_init<<<gN, 256>>>(ei);
    k_hist<<<gE, 256>>>(ei);
    k_scan<<<1, 1024>>>();
    k_fill<<<gE, 256>>>(ei);

    // layer 1
    gemm_tf32<<<gB, 256>>>(x, W1, hs, M);
    aggregate<<<gAg, 256>>>(hs, b1, x1);
    // layer 2
    gemm_tf32<<<gB, 256>>>(x1, W2, hs, M);
    aggregate<<<gAg, 256>>>(hs, b2, x2);
    // output projection on (x1 + x2)
    gemm_out_tf32<<<gB, 256>>>(x1, x2, Wo, bo, out, M);
}

// round 3
// speedup vs baseline: 1.9472x; 1.8520x over previous
#include <cuda_runtime.h>
#include <mma.h>
#include <math.h>

using namespace nvcuda;

#define N_NODES 100000
#define N_PAD   100096
#define N_EDGES 1600000
#define CHN 128
#define OUTCH 64
#define SCAN_T 512
#define SCAN_NB ((N_NODES + SCAN_T - 1) / SCAN_T)   // 196

// ---------------- device scratch ------------------------------------------
__device__ int   g_is64;
__device__ int   g_cnt[N_NODES];
__device__ int   g_row[N_NODES + 1];
__device__ int   g_cur[N_NODES];
__device__ float g_dis[N_NODES];
__device__ int   g_csr[N_EDGES];
__device__ int   g_bsum[SCAN_NB];
__device__ int   g_boff[SCAN_NB];
__device__ float g_hs[N_PAD * CHN];
__device__ float g_x1[N_PAD * CHN];
__device__ float g_x2[N_PAD * CHN];

// ---------------- edge dtype sniff (parallel) ------------------------------
__global__ void k_sniff(const void* __restrict__ edges) {
    __shared__ int cnt;
    if (threadIdx.x == 0) cnt = 0;
    __syncthreads();
    const int* p = (const int*)edges;
    int z = (p[2 * threadIdx.x + 1] == 0) ? 1 : 0;
    unsigned b = __ballot_sync(0xffffffff, z);
    if ((threadIdx.x & 31) == 0) atomicAdd(&cnt, __popc(b));
    __syncthreads();
    if (threadIdx.x == 0) g_is64 = (cnt > 512) ? 1 : 0;
}

__global__ void k_hist(const void* __restrict__ edges) {
    int i = blockIdx.x * blockDim.x + threadIdx.x;
    if (i >= N_EDGES) return;
    int d;
    if (g_is64) d = (int)((const long long*)edges)[N_EDGES + i];
    else        d = ((const int*)edges)[N_EDGES + i];
    atomicAdd(&g_cnt[d], 1);
}

// ---------------- 3-phase parallel scan ------------------------------------
__global__ void k_scan1() {
    __shared__ int s[SCAN_T];
    int i = blockIdx.x * SCAN_T + threadIdx.x;
    int v = (i < N_NODES) ? g_cnt[i] : 0;
    s[threadIdx.x] = v;
    __syncthreads();
    for (int off = SCAN_T / 2; off > 0; off >>= 1) {
        if (threadIdx.x < off) s[threadIdx.x] += s[threadIdx.x + off];
        __syncthreads();
    }
    if (threadIdx.x == 0) g_bsum[blockIdx.x] = s[0];
}

__global__ void k_scan2() {
    __shared__ int s[256];
    int t = threadIdx.x;
    int v = (t < SCAN_NB) ? g_bsum[t] : 0;
    s[t] = v;
    __syncthreads();
    for (int off = 1; off < 256; off <<= 1) {
        int u = (t >= off) ? s[t - off] : 0;
        __syncthreads();
        s[t] += u;
        __syncthreads();
    }
    if (t < SCAN_NB) g_boff[t] = s[t] - v;
}

__global__ void k_scan3() {
    __shared__ int s[SCAN_T];
    int t = threadIdx.x;
    int i = blockIdx.x * SCAN_T + t;
    int c = (i < N_NODES) ? g_cnt[i] : 0;
    s[t] = c;
    __syncthreads();
    for (int off = 1; off < SCAN_T; off <<= 1) {
        int u = (t >= off) ? s[t - off] : 0;
        __syncthreads();
        s[t] += u;
        __syncthreads();
    }
    if (i < N_NODES) {
        int excl = g_boff[blockIdx.x] + s[t] - c;
        g_row[i] = excl;
        g_cur[i] = excl;
        g_dis[i] = rsqrtf((float)(c + 1));
        if (i == N_NODES - 1) g_row[N_NODES] = excl + c;
    }
}

__global__ void k_fill(const void* __restrict__ edges) {
    int i = blockIdx.x * blockDim.x + threadIdx.x;
    if (i >= N_EDGES) return;
    int sN, dN;
    if (g_is64) {
        const long long* p = (const long long*)edges;
        sN = (int)p[i]; dN = (int)p[N_EDGES + i];
    } else {
        const int* p = (const int*)edges;
        sN = p[i]; dN = p[N_EDGES + i];
    }
    int idx = atomicAdd(&g_cur[dN], 1);
    g_csr[idx] = sN;
}

// ---------------- tf32 GEMM: A[M,128] @ B[128,128], 192-row tile ----------
// tf32 conversion happens once, at smem store.
__global__ __launch_bounds__(256) void gemm_tf32(
    const float* __restrict__ A, const float* __restrict__ B,
    float* __restrict__ out, int M)
{
    __shared__ float As[192][36];   // [rows][K-chunk 32 + pad]
    __shared__ float Bs[32][136];
    int tid = threadIdx.x;
    int wid = tid >> 5;
    int wm = wid & 3;               // 4 row groups x 48 rows
    int wn = wid >> 2;              // 2 col groups x 64 cols
    int bm = blockIdx.x * 192;

    wmma::fragment<wmma::accumulator, 16, 16, 8, float> acc[3][4];
#pragma unroll
    for (int i = 0; i < 3; i++)
#pragma unroll
        for (int j = 0; j < 4; j++) wmma::fill_fragment(acc[i][j], 0.f);

    for (int k0 = 0; k0 < 128; k0 += 32) {
        // As: 192x32 floats = 1536 float4 -> 6 per thread
#pragma unroll
        for (int h = 0; h < 6; h++) {
            int i4 = tid + h * 256;
            int r = i4 >> 3, c = (i4 & 7) * 4;
            float4 v = make_float4(0.f, 0.f, 0.f, 0.f);
            if (bm + r < M) v = *(const float4*)(A + (long)(bm + r) * 128 + k0 + c);
            As[r][c + 0] = wmma::__float_to_tf32(v.x);
            As[r][c + 1] = wmma::__float_to_tf32(v.y);
            As[r][c + 2] = wmma::__float_to_tf32(v.z);
            As[r][c + 3] = wmma::__float_to_tf32(v.w);
        }
        // Bs: 32x128 floats = 1024 float4 -> 4 per thread
#pragma unroll
        for (int h = 0; h < 4; h++) {
            int i4 = tid + h * 256;
            int r = i4 >> 5, c = (i4 & 31) * 4;
            float4 v = *(const float4*)(B + (long)(k0 + r) * 128 + c);
            Bs[r][c + 0] = wmma::__float_to_tf32(v.x);
            Bs[r][c + 1] = wmma::__float_to_tf32(v.y);
            Bs[r][c + 2] = wmma::__float_to_tf32(v.z);
            Bs[r][c + 3] = wmma::__float_to_tf32(v.w);
        }
        __syncthreads();
#pragma unroll
        for (int kk = 0; kk < 4; kk++) {
            wmma::fragment<wmma::matrix_a, 16, 16, 8, wmma::precision::tf32, wmma::row_major> af[3];
            wmma::fragment<wmma::matrix_b, 16, 16, 8, wmma::precision::tf32, wmma::row_major> bf[4];
#pragma unroll
            for (int i = 0; i < 3; i++)
                wmma::load_matrix_sync(af[i], &As[wm * 48 + i * 16][kk * 8], 36);
#pragma unroll
            for (int j = 0; j < 4; j++)
                wmma::load_matrix_sync(bf[j], &Bs[kk * 8][wn * 64 + j * 16], 136);
#pragma unroll
            for (int i = 0; i < 3; i++)
#pragma unroll
                for (int j = 0; j < 4; j++)
                    wmma::mma_sync(acc[i][j], af[i], bf[j], acc[i][j]);
        }
        __syncthreads();
    }
#pragma unroll
    for (int i = 0; i < 3; i++)
#pragma unroll
        for (int j = 0; j < 4; j++) {
            int r = bm + wm * 48 + i * 16;
            if (r < N_PAD - 16)
                wmma::store_matrix_sync(out + (long)r * 128 + wn * 64 + j * 16,
                                        acc[i][j], 128, wmma::mem_row_major);
        }
}

// ---------------- tf32 output GEMM: (x1+x2)[M,128] @ Wo[128,64] + bo ------
__global__ __launch_bounds__(256) void gemm_out_tf32(
    const float* __restrict__ A1, const float* __restrict__ A2,
    const float* __restrict__ B, const float* __restrict__ bias,
    float* __restrict__ out, int M)
{
    __shared__ float As[128][36];
    __shared__ float Bs[32][72];
    __shared__ float Bt[16][72];
    int tid = threadIdx.x;
    int wid = tid >> 5;
    int bm = blockIdx.x * 128;

    for (int i = tid; i < 16 * 64; i += 256) Bt[i >> 6][i & 63] = bias[i & 63];
    __syncthreads();

    wmma::fragment<wmma::accumulator, 16, 16, 8, float> acc[4];
#pragma unroll
    for (int j = 0; j < 4; j++)
        wmma::load_matrix_sync(acc[j], &Bt[0][j * 16], 72, wmma::mem_row_major);

    for (int k0 = 0; k0 < 128; k0 += 32) {
#pragma unroll
        for (int h = 0; h < 4; h++) {
            int i4 = tid + h * 256;
            int r = i4 >> 3, c = (i4 & 7) * 4;
            float4 v = make_float4(0.f, 0.f, 0.f, 0.f);
            if (bm + r < M) {
                float4 u = *(const float4*)(A1 + (long)(bm + r) * 128 + k0 + c);
                float4 w = *(const float4*)(A2 + (long)(bm + r) * 128 + k0 + c);
                v.x = u.x + w.x; v.y = u.y + w.y; v.z = u.z + w.z; v.w = u.w + w.w;
            }
            As[r][c + 0] = wmma::__float_to_tf32(v.x);
            As[r][c + 1] = wmma::__float_to_tf32(v.y);
            As[r][c + 2] = wmma::__float_to_tf32(v.z);
            As[r][c + 3] = wmma::__float_to_tf32(v.w);
        }
        {
            int r = tid >> 4, c = (tid & 15) * 4;
            float4 v = *(const float4*)(B + (long)(k0 + r) * 64 + c);
            Bs[r][c + 0] = wmma::__float_to_tf32(v.x);
            Bs[r][c + 1] = wmma::__float_to_tf32(v.y);
            Bs[r][c + 2] = wmma::__float_to_tf32(v.z);
            Bs[r][c + 3] = wmma::__float_to_tf32(v.w);
            r = (tid + 256) >> 4; c = ((tid + 256) & 15) * 4;
            v = *(const float4*)(B + (long)(k0 + r) * 64 + c);
            Bs[r][c + 0] = wmma::__float_to_tf32(v.x);
            Bs[r][c + 1] = wmma::__float_to_tf32(v.y);
            Bs[r][c + 2] = wmma::__float_to_tf32(v.z);
            Bs[r][c + 3] = wmma::__float_to_tf32(v.w);
        }
        __syncthreads();
#pragma unroll
        for (int kk = 0; kk < 4; kk++) {
            wmma::fragment<wmma::matrix_a, 16, 16, 8, wmma::precision::tf32, wmma::row_major> af;
            wmma::fragment<wmma::matrix_b, 16, 16, 8, wmma::precision::tf32, wmma::row_major> bf[4];
            wmma::load_matrix_sync(af, &As[wid * 16][kk * 8], 36);
#pragma unroll
            for (int j = 0; j < 4; j++)
                wmma::load_matrix_sync(bf[j], &Bs[kk * 8][j * 16], 72);
#pragma unroll
            for (int j = 0; j < 4; j++)
                wmma::mma_sync(acc[j], af, bf[j], acc[j]);
        }
        __syncthreads();
    }
    int r = bm + wid * 16;
    if (r + 16 <= M) {
#pragma unroll
        for (int j = 0; j < 4; j++)
            wmma::store_matrix_sync(out + (long)r * 64 + j * 16,
                                    acc[j], 64, wmma::mem_row_major);
    }
}

// ---------------- aggregation: warp per node, 4-way unroll ----------------
__global__ __launch_bounds__(256) void aggregate(
    const float* __restrict__ hs, const float* __restrict__ bias,
    float* __restrict__ xo)
{
    int gw = (blockIdx.x * blockDim.x + threadIdx.x) >> 5;
    int lane = threadIdx.x & 31;
    if (gw >= N_NODES) return;
    int beg = g_row[gw];
    int end = g_row[gw + 1];
    float dd = g_dis[gw];
    float4 self = *(const float4*)(hs + (long)gw * 128 + lane * 4);
    float4 acc;
    acc.x = self.x * dd; acc.y = self.y * dd; acc.z = self.z * dd; acc.w = self.w * dd;
    int e = beg;
    for (; e + 4 <= end; e += 4) {
        int s0 = g_csr[e], s1 = g_csr[e + 1], s2 = g_csr[e + 2], s3 = g_csr[e + 3];
        float d0 = g_dis[s0], d1 = g_dis[s1], d2 = g_dis[s2], d3 = g_dis[s3];
        float4 v0 = *(const float4*)(hs + (long)s0 * 128 + lane * 4);
        float4 v1 = *(const float4*)(hs + (long)s1 * 128 + lane * 4);
        float4 v2 = *(const float4*)(hs + (long)s2 * 128 + lane * 4);
        float4 v3 = *(const float4*)(hs + (long)s3 * 128 + lane * 4);
        acc.x += v0.x * d0 + v1.x * d1 + v2.x * d2 + v3.x * d3;
        acc.y += v0.y * d0 + v1.y * d1 + v2.y * d2 + v3.y * d3;
        acc.z += v0.z * d0 + v1.z * d1 + v2.z * d2 + v3.z * d3;
        acc.w += v0.w * d0 + v1.w * d1 + v2.w * d2 + v3.w * d3;
    }
    for (; e < end; e++) {
        int s = g_csr[e];
        float ds = g_dis[s];
        float4 v = *(const float4*)(hs + (long)s * 128 + lane * 4);
        acc.x += v.x * ds; acc.y += v.y * ds; acc.z += v.z * ds; acc.w += v.w * ds;
    }
    float4 b = *(const float4*)(bias + lane * 4);
    float4 o;
    o.x = fmaxf(acc.x * dd + b.x, 0.f);
    o.y = fmaxf(acc.y * dd + b.y, 0.f);
    o.z = fmaxf(acc.z * dd + b.z, 0.f);
    o.w = fmaxf(acc.w * dd + b.w, 0.f);
    *(float4*)(xo + (long)gw * 128 + lane * 4) = o;
}

// ---------------- launch ---------------------------------------------------
extern "C" void kernel_launch(void* const* d_in, const int* in_sizes, int n_in,
                              void* d_out, int out_size)
{
    const float* x  = (const float*)d_in[0];
    const void*  ei = d_in[1];
    const float* W1 = (const float*)d_in[2];
    const float* b1 = (const float*)d_in[3];
    const float* W2 = (const float*)d_in[4];
    const float* b2 = (const float*)d_in[5];
    const float* Wo = (const float*)d_in[6];
    const float* bo = (const float*)d_in[7];
    float* out = (float*)d_out;

    float *hs, *x1, *x2;
    int* cnt;
    cudaGetSymbolAddress((void**)&hs,  g_hs);
    cudaGetSymbolAddress((void**)&x1,  g_x1);
    cudaGetSymbolAddress((void**)&x2,  g_x2);
    cudaGetSymbolAddress((void**)&cnt, g_cnt);

    const int M = N_NODES;
    int gB  = (M + 191) / 192;
    int gBo = (M + 127) / 128;
    int gE  = (N_EDGES + 255) / 256;
    int gAg = (M * 32 + 255) / 256;

    // CSR build + normalization
    cudaMemsetAsync(cnt, 0, N_NODES * sizeof(int));
    k_sniff<<<1, 1024>>>(ei);
    k_hist<<<gE, 256>>>(ei);
    k_scan1<<<SCAN_NB, SCAN_T>>>();
    k_scan2<<<1, 256>>>();
    k_scan3<<<SCAN_NB, SCAN_T>>>();
    k_fill<<<gE, 256>>>(ei);

    // layer 1
    gemm_tf32<<<gB, 256>>>(x, W1, hs, M);
    aggregate<<<gAg, 256>>>(hs, b1, x1);
    // layer 2
    gemm_tf32<<<gB, 256>>>(x1, W2, hs, M);
    aggregate<<<gAg, 256>>>(hs, b2, x2);
    // output projection on (x1 + x2)
    gemm_out_tf32<<<gBo, 256>>>(x1, x2, Wo, bo, out, M);
}

// round 5
// speedup vs baseline: 2.0761x; 1.0662x over previous
#include <cuda_runtime.h>
#include <cuda_fp16.h>
#include <mma.h>
#include <math.h>

using namespace nvcuda;

#define N_NODES 100000
#define N_PAD   100096
#define N_EDGES 1600000
#define CHN 128
#define OUTCH 64
#define SCAN_T 512
#define SCAN_NB ((N_NODES + SCAN_T - 1) / SCAN_T)   // 196

// ---------------- device scratch ------------------------------------------
__device__ int    g_is64;
__device__ int    g_cnt[N_NODES];
__device__ int    g_row[N_NODES + 1];
__device__ int    g_cur[N_NODES];
__device__ float  g_dis[N_NODES];
__device__ int    g_csr[N_EDGES];
__device__ int    g_bsum[SCAN_NB];
__device__ int    g_boff[SCAN_NB];
__device__ __half g_hs[N_PAD * CHN];
__device__ float  g_x1[N_PAD * CHN];
__device__ float  g_x2[N_PAD * CHN];

// ---------------- edge dtype sniff (parallel) ------------------------------
__global__ void k_sniff(const void* __restrict__ edges) {
    __shared__ int cnt;
    if (threadIdx.x == 0) cnt = 0;
    __syncthreads();
    const int* p = (const int*)edges;
    int z = (p[2 * threadIdx.x + 1] == 0) ? 1 : 0;
    unsigned b = __ballot_sync(0xffffffff, z);
    if ((threadIdx.x & 31) == 0) atomicAdd(&cnt, __popc(b));
    __syncthreads();
    if (threadIdx.x == 0) g_is64 = (cnt > 512) ? 1 : 0;
}

__global__ void k_hist(const void* __restrict__ edges) {
    int base = (blockIdx.x * blockDim.x + threadIdx.x) * 4;
    int is64 = g_is64;
#pragma unroll
    for (int u = 0; u < 4; u++) {
        int i = base + u;
        if (i >= N_EDGES) break;
        int d;
        if (is64) d = (int)((const long long*)edges)[N_EDGES + i];
        else      d = ((const int*)edges)[N_EDGES + i];
        atomicAdd(&g_cnt[d], 1);
    }
}

// ---------------- 3-phase parallel scan ------------------------------------
__global__ void k_scan1() {
    __shared__ int s[SCAN_T];
    int i = blockIdx.x * SCAN_T + threadIdx.x;
    int v = (i < N_NODES) ? g_cnt[i] : 0;
    s[threadIdx.x] = v;
    __syncthreads();
    for (int off = SCAN_T / 2; off > 0; off >>= 1) {
        if (threadIdx.x < off) s[threadIdx.x] += s[threadIdx.x + off];
        __syncthreads();
    }
    if (threadIdx.x == 0) g_bsum[blockIdx.x] = s[0];
}

__global__ void k_scan2() {
    __shared__ int s[256];
    int t = threadIdx.x;
    int v = (t < SCAN_NB) ? g_bsum[t] : 0;
    s[t] = v;
    __syncthreads();
    for (int off = 1; off < 256; off <<= 1) {
        int u = (t >= off) ? s[t - off] : 0;
        __syncthreads();
        s[t] += u;
        __syncthreads();
    }
    if (t < SCAN_NB) g_boff[t] = s[t] - v;
}

__global__ void k_scan3() {
    __shared__ int s[SCAN_T];
    int t = threadIdx.x;
    int i = blockIdx.x * SCAN_T + t;
    int c = (i < N_NODES) ? g_cnt[i] : 0;
    s[t] = c;
    __syncthreads();
    for (int off = 1; off < SCAN_T; off <<= 1) {
        int u = (t >= off) ? s[t - off] : 0;
        __syncthreads();
        s[t] += u;
        __syncthreads();
    }
    if (i < N_NODES) {
        int excl = g_boff[blockIdx.x] + s[t] - c;
        g_row[i] = excl;
        g_cur[i] = excl;
        g_dis[i] = rsqrtf((float)(c + 1));
        if (i == N_NODES - 1) g_row[N_NODES] = excl + c;
    }
}

__global__ void k_fill(const void* __restrict__ edges) {
    int base = (blockIdx.x * blockDim.x + threadIdx.x) * 4;
    int is64 = g_is64;
#pragma unroll
    for (int u = 0; u < 4; u++) {
        int i = base + u;
        if (i >= N_EDGES) break;
        int sN, dN;
        if (is64) {
            const long long* p = (const long long*)edges;
            sN = (int)p[i]; dN = (int)p[N_EDGES + i];
        } else {
            const int* p = (const int*)edges;
            sN = p[i]; dN = p[N_EDGES + i];
        }
        int idx = atomicAdd(&g_cur[dN], 1);
        g_csr[idx] = sN;
    }
}

// ---------------- tf32 GEMM: A[M,128] @ B[128,128] -> half out ------------
#define AS_FLOATS (192 * 36)
#define BS_FLOATS (32 * 136)

__global__ __launch_bounds__(256) void gemm_tf32(
    const float* __restrict__ A, const float* __restrict__ B,
    __half* __restrict__ out, int M)
{
    __shared__ float pool[AS_FLOATS + BS_FLOATS];   // 45056 B
    float (*As)[36]  = (float(*)[36])pool;
    float (*Bs)[136] = (float(*)[136])(pool + AS_FLOATS);
    // epilogue staging aliases the As region (dead after last k-loop sync)
    float (*stage)[16][20] = (float(*)[16][20])pool;

    int tid = threadIdx.x;
    int wid = tid >> 5;
    int lane = tid & 31;
    int wm = wid & 3;
    int wn = wid >> 2;
    int bm = blockIdx.x * 192;

    wmma::fragment<wmma::accumulator, 16, 16, 8, float> acc[3][4];
#pragma unroll
    for (int i = 0; i < 3; i++)
#pragma unroll
        for (int j = 0; j < 4; j++) wmma::fill_fragment(acc[i][j], 0.f);

    for (int k0 = 0; k0 < 128; k0 += 32) {
#pragma unroll
        for (int h = 0; h < 6; h++) {
            int i4 = tid + h * 256;
            int r = i4 >> 3, c = (i4 & 7) * 4;
            float4 v = make_float4(0.f, 0.f, 0.f, 0.f);
            if (bm + r < M) v = *(const float4*)(A + (long)(bm + r) * 128 + k0 + c);
            As[r][c + 0] = wmma::__float_to_tf32(v.x);
            As[r][c + 1] = wmma::__float_to_tf32(v.y);
            As[r][c + 2] = wmma::__float_to_tf32(v.z);
            As[r][c + 3] = wmma::__float_to_tf32(v.w);
        }
#pragma unroll
        for (int h = 0; h < 4; h++) {
            int i4 = tid + h * 256;
            int r = i4 >> 5, c = (i4 & 31) * 4;
            float4 v = *(const float4*)(B + (long)(k0 + r) * 128 + c);
            Bs[r][c + 0] = wmma::__float_to_tf32(v.x);
            Bs[r][c + 1] = wmma::__float_to_tf32(v.y);
            Bs[r][c + 2] = wmma::__float_to_tf32(v.z);
            Bs[r][c + 3] = wmma::__float_to_tf32(v.w);
        }
        __syncthreads();
#pragma unroll
        for (int kk = 0; kk < 4; kk++) {
            wmma::fragment<wmma::matrix_a, 16, 16, 8, wmma::precision::tf32, wmma::row_major> af[3];
            wmma::fragment<wmma::matrix_b, 16, 16, 8, wmma::precision::tf32, wmma::row_major> bf[4];
#pragma unroll
            for (int i = 0; i < 3; i++)
                wmma::load_matrix_sync(af[i], &As[wm * 48 + i * 16][kk * 8], 36);
#pragma unroll
            for (int j = 0; j < 4; j++)
                wmma::load_matrix_sync(bf[j], &Bs[kk * 8][wn * 64 + j * 16], 136);
#pragma unroll
            for (int i = 0; i < 3; i++)
#pragma unroll
                for (int j = 0; j < 4; j++)
                    wmma::mma_sync(acc[i][j], af[i], bf[j], acc[i][j]);
        }
        __syncthreads();
    }
    // epilogue: stage each 16x16 fragment (ldm=20, multiple of 4), half-pack
#pragma unroll
    for (int i = 0; i < 3; i++)
#pragma unroll
        for (int j = 0; j < 4; j++) {
            wmma::store_matrix_sync(&stage[wid][0][0], acc[i][j], 20, wmma::mem_row_major);
            __syncwarp();
            int r = bm + wm * 48 + i * 16 + (lane >> 1);        // always < N_PAD
            const float* srow = &stage[wid][lane >> 1][(lane & 1) * 8];
            __half2 h0 = __float22half2_rn(make_float2(srow[0], srow[1]));
            __half2 h1 = __float22half2_rn(make_float2(srow[2], srow[3]));
            __half2 h2 = __float22half2_rn(make_float2(srow[4], srow[5]));
            __half2 h3 = __float22half2_rn(make_float2(srow[6], srow[7]));
            uint4 pack;
            pack.x = *(unsigned*)&h0;
            pack.y = *(unsigned*)&h1;
            pack.z = *(unsigned*)&h2;
            pack.w = *(unsigned*)&h3;
            *(uint4*)(out + (long)r * 128 + wn * 64 + j * 16 + (lane & 1) * 8) = pack;
            __syncwarp();
        }
}

// ---------------- tf32 output GEMM: (x1+x2)[M,128] @ Wo[128,64] + bo ------
__global__ __launch_bounds__(256) void gemm_out_tf32(
    const float* __restrict__ A1, const float* __restrict__ A2,
    const float* __restrict__ B, const float* __restrict__ bias,
    float* __restrict__ out, int M)
{
    __shared__ float As[128][36];
    __shared__ float Bs[32][72];
    __shared__ float Bt[16][72];
    int tid = threadIdx.x;
    int wid = tid >> 5;
    int bm = blockIdx.x * 128;

    for (int i = tid; i < 16 * 64; i += 256) Bt[i >> 6][i & 63] = bias[i & 63];
    __syncthreads();

    wmma::fragment<wmma::accumulator, 16, 16, 8, float> acc[4];
#pragma unroll
    for (int j = 0; j < 4; j++)
        wmma::load_matrix_sync(acc[j], &Bt[0][j * 16], 72, wmma::mem_row_major);

    for (int k0 = 0; k0 < 128; k0 += 32) {
#pragma unroll
        for (int h = 0; h < 4; h++) {
            int i4 = tid + h * 256;
            int r = i4 >> 3, c = (i4 & 7) * 4;
            float4 v = make_float4(0.f, 0.f, 0.f, 0.f);
            if (bm + r < M) {
                float4 u = *(const float4*)(A1 + (long)(bm + r) * 128 + k0 + c);
                float4 w = *(const float4*)(A2 + (long)(bm + r) * 128 + k0 + c);
                v.x = u.x + w.x; v.y = u.y + w.y; v.z = u.z + w.z; v.w = u.w + w.w;
            }
            As[r][c + 0] = wmma::__float_to_tf32(v.x);
            As[r][c + 1] = wmma::__float_to_tf32(v.y);
            As[r][c + 2] = wmma::__float_to_tf32(v.z);
            As[r][c + 3] = wmma::__float_to_tf32(v.w);
        }
        {
            int r = tid >> 4, c = (tid & 15) * 4;
            float4 v = *(const float4*)(B + (long)(k0 + r) * 64 + c);
            Bs[r][c + 0] = wmma::__float_to_tf32(v.x);
            Bs[r][c + 1] = wmma::__float_to_tf32(v.y);
            Bs[r][c + 2] = wmma::__float_to_tf32(v.z);
            Bs[r][c + 3] = wmma::__float_to_tf32(v.w);
            r = (tid + 256) >> 4; c = ((tid + 256) & 15) * 4;
            v = *(const float4*)(B + (long)(k0 + r) * 64 + c);
            Bs[r][c + 0] = wmma::__float_to_tf32(v.x);
            Bs[r][c + 1] = wmma::__float_to_tf32(v.y);
            Bs[r][c + 2] = wmma::__float_to_tf32(v.z);
            Bs[r][c + 3] = wmma::__float_to_tf32(v.w);
        }
        __syncthreads();
#pragma unroll
        for (int kk = 0; kk < 4; kk++) {
            wmma::fragment<wmma::matrix_a, 16, 16, 8, wmma::precision::tf32, wmma::row_major> af;
            wmma::fragment<wmma::matrix_b, 16, 16, 8, wmma::precision::tf32, wmma::row_major> bf[4];
            wmma::load_matrix_sync(af, &As[wid * 16][kk * 8], 36);
#pragma unroll
            for (int j = 0; j < 4; j++)
                wmma::load_matrix_sync(bf[j], &Bs[kk * 8][j * 16], 72);
#pragma unroll
            for (int j = 0; j < 4; j++)
                wmma::mma_sync(acc[j], af, bf[j], acc[j]);
        }
        __syncthreads();
    }
    int r = bm + wid * 16;
    if (r + 16 <= M) {
#pragma unroll
        for (int j = 0; j < 4; j++)
            wmma::store_matrix_sync(out + (long)r * 64 + j * 16,
                                    acc[j], 64, wmma::mem_row_major);
    }
}

// ---------------- aggregation: warp per node, half gather, fp32 accum -----
__device__ __forceinline__ float4 gather_h(const __half* hs, int s, int lane) {
    uint2 raw = *(const uint2*)(hs + (long)s * 128 + lane * 4);
    float2 a = __half22float2(*(__half2*)&raw.x);
    float2 b = __half22float2(*(__half2*)&raw.y);
    return make_float4(a.x, a.y, b.x, b.y);
}

__global__ __launch_bounds__(256) void aggregate(
    const __half* __restrict__ hs, const float* __restrict__ bias,
    float* __restrict__ xo)
{
    int gw = (blockIdx.x * blockDim.x + threadIdx.x) >> 5;
    int lane = threadIdx.x & 31;
    if (gw >= N_NODES) return;
    int beg = g_row[gw];
    int end = g_row[gw + 1];
    float dd = g_dis[gw];
    float4 self = gather_h(hs, gw, lane);
    float4 acc;
    acc.x = self.x * dd; acc.y = self.y * dd; acc.z = self.z * dd; acc.w = self.w * dd;
    int e = beg;
    for (; e + 4 <= end; e += 4) {
        int s0 = g_csr[e], s1 = g_csr[e + 1], s2 = g_csr[e + 2], s3 = g_csr[e + 3];
        float d0 = g_dis[s0], d1 = g_dis[s1], d2 = g_dis[s2], d3 = g_dis[s3];
        float4 v0 = gather_h(hs, s0, lane);
        float4 v1 = gather_h(hs, s1, lane);
        float4 v2 = gather_h(hs, s2, lane);
        float4 v3 = gather_h(hs, s3, lane);
        acc.x += v0.x * d0 + v1.x * d1 + v2.x * d2 + v3.x * d3;
        acc.y += v0.y * d0 + v1.y * d1 + v2.y * d2 + v3.y * d3;
        acc.z += v0.z * d0 + v1.z * d1 + v2.z * d2 + v3.z * d3;
        acc.w += v0.w * d0 + v1.w * d1 + v2.w * d2 + v3.w * d3;
    }
    for (; e < end; e++) {
        int s = g_csr[e];
        float ds = g_dis[s];
        float4 v = gather_h(hs, s, lane);
        acc.x += v.x * ds; acc.y += v.y * ds; acc.z += v.z * ds; acc.w += v.w * ds;
    }
    float4 b = *(const float4*)(bias + lane * 4);
    float4 o;
    o.x = fmaxf(acc.x * dd + b.x, 0.f);
    o.y = fmaxf(acc.y * dd + b.y, 0.f);
    o.z = fmaxf(acc.z * dd + b.z, 0.f);
    o.w = fmaxf(acc.w * dd + b.w, 0.f);
    *(float4*)(xo + (long)gw * 128 + lane * 4) = o;
}

// ---------------- launch ---------------------------------------------------
extern "C" void kernel_launch(void* const* d_in, const int* in_sizes, int n_in,
                              void* d_out, int out_size)
{
    const float* x  = (const float*)d_in[0];
    const void*  ei = d_in[1];
    const float* W1 = (const float*)d_in[2];
    const float* b1 = (const float*)d_in[3];
    const float* W2 = (const float*)d_in[4];
    const float* b2 = (const float*)d_in[5];
    const float* Wo = (const float*)d_in[6];
    const float* bo = (const float*)d_in[7];
    float* out = (float*)d_out;

    __half* hs;
    float *x1, *x2;
    int* cnt;
    cudaGetSymbolAddress((void**)&hs,  g_hs);
    cudaGetSymbolAddress((void**)&x1,  g_x1);
    cudaGetSymbolAddress((void**)&x2,  g_x2);
    cudaGetSymbolAddress((void**)&cnt, g_cnt);

    const int M = N_NODES;
    int gB  = (M + 191) / 192;
    int gBo = (M + 127) / 128;
    int gE4 = (N_EDGES + 1023) / 1024;
    int gAg = (M * 32 + 255) / 256;

    cudaMemsetAsync(cnt, 0, N_NODES * sizeof(int));
    k_sniff<<<1, 1024>>>(ei);
    k_hist<<<gE4, 256>>>(ei);
    k_scan1<<<SCAN_NB, SCAN_T>>>();
    k_scan2<<<1, 256>>>();
    k_scan3<<<SCAN_NB, SCAN_T>>>();
    k_fill<<<gE4, 256>>>(ei);

    gemm_tf32<<<gB, 256>>>(x, W1, hs, M);
    aggregate<<<gAg, 256>>>(hs, b1, x1);
    gemm_tf32<<<gB, 256>>>(x1, W2, hs, M);
    aggregate<<<gAg, 256>>>(hs, b2, x2);
    gemm_out_tf32<<<gBo, 256>>>(x1, x2, Wo, bo, out, M);
}